// round 11
// baseline (speedup 1.0000x reference)
#include <cuda_runtime.h>
#include <cuda_fp16.h>
#include <stdint.h>

#define XD 128
#define YD 128
#define ZD 8
#define NTOK 131072          // XD*YD*ZD
#define BB 2
#define C 128
#define HEADS 8
#define LEVELS 3
#define POINTS 4
#define NOFF 192             // HEADS*LEVELS*POINTS*2
#define NW 96                // HEADS*LEVELS*POINTS
#define NCOL 288             // NOFF+NW
#define NPIX 9507
#define H0 47
#define W0 153
#define H1 24
#define W1 77
#define H2 12
#define W2 39
#define S1 7191              // H0*W0
#define S2 9039              // S1 + H1*W1

#define TOK 16
#define THR 256
#define NV 298               // ceil(BB*NPIX / 64) value blocks in fused kernel
#define NFILL 8192           // (NTOK/32)*BB fill blocks
#define NSCAT 1024           // scatter blocks (BB*NTOK/256)
#define ZPAD (BB * NPIX * C) // index of the permanently-zero pad row

// ---------------- scratch (static device globals; no allocation) ----------------
__device__ float g_value[(size_t)BB * NPIX * C + C];   // +C: zero pad row (never written)
__device__ int g_mask[BB * NTOK];
__device__ int g_list[BB * NTOK];
__device__ int g_cnt;
__device__ int g_tile;

// ---------------- K1: zero mask + counters ----------------
__global__ void k_zero() {
    int i = blockIdx.x * blockDim.x + threadIdx.x;   // 65536 threads x int4
    ((int4*)g_mask)[i] = make_int4(0, 0, 0, 0);
    if (i == 0) { g_cnt = 0; g_tile = 0; }
}

// ---------------- K2 (fused): value projection + fill/transpose + scatter/compact ----------------
// blocks [0, NV): value projection, 64 px/block, Wv cached in smem in 32-k chunks
// blocks [NV, NV+NFILL): transpose scene_embed into out (swizzled, float4 both sides)
// blocks [NV+NFILL, NV+NFILL+NSCAT): scatter vol_pts -> mask -> compact list
__global__ void __launch_bounds__(THR) k_fillvalue(
    const float4* __restrict__ embed4, float4* __restrict__ out4,
    const float* __restrict__ f0, const float* __restrict__ f1, const float* __restrict__ f2,
    const float* __restrict__ Wv, const float* __restrict__ bv,
    const int* __restrict__ vol)
{
    extern __shared__ __align__(16) char smbuf[];
    const int t = threadIdx.x;

    if (blockIdx.x >= NV + NFILL) {
        // ================= scatter + compact =================
        int i = (blockIdx.x - NV - NFILL) * THR + t;
        int x = vol[3 * i], y = vol[3 * i + 1], z = vol[3 * i + 2];
        if ((unsigned)x < XD && (unsigned)y < YD && (unsigned)z < ZD) {
            int b = i >> 17;
            int v = b * NTOK + x * (YD * ZD) + y * ZD + z;
            if (atomicExch(&g_mask[v], 1) == 0) {
                int p = atomicAdd(&g_cnt, 1);
                g_list[p] = v;
            }
        }
        return;
    }

    if (blockIdx.x < NV) {
        // ================= value projection =================
        float (*fs)[64] = (float(*)[64])smbuf;            // 32 KB
        float* Wvs = (float*)(smbuf + 32768);             // 16 KB: [32][128]
        __shared__ const float* ptrs[64];
        __shared__ int strd[64];
        const int r0 = blockIdx.x * 64;
        const int total = BB * NPIX;

        if (t < 64) {
            int row = r0 + t;
            if (row < total) {
                int b = row / NPIX, pix = row % NPIX;
                const float* f; int HW, hw;
                if (pix < S1)      { f = f0; HW = H0 * W0; hw = pix; }
                else if (pix < S2) { f = f1; HW = H1 * W1; hw = pix - S1; }
                else               { f = f2; HW = H2 * W2; hw = pix - S2; }
                ptrs[t] = f + (size_t)b * C * HW + hw;
                strd[t] = HW;
            } else { ptrs[t] = f0; strd[t] = 0; }
        }
        __syncthreads();

#pragma unroll
        for (int i = 0; i < 32; i++) {                    // C*64/THR = 32 loads/thread
            int idx = t + i * THR;
            int k = idx >> 6, j = idx & 63;
            fs[k][j] = ptrs[j][(size_t)k * strd[j]];
        }
        __syncthreads();

        const int cg = t & 31;                            // float4 channel group
        const int p0 = (t >> 5) * 8;                      // 8 pixels
        float acc[4][8];
#pragma unroll
        for (int ci = 0; ci < 4; ci++)
#pragma unroll
            for (int p = 0; p < 8; p++) acc[ci][p] = 0.f;

        for (int kc = 0; kc < 4; kc++) {
            const float4* Wg = (const float4*)(Wv + kc * 32 * C);
            float4* Ws4 = (float4*)Wvs;
#pragma unroll
            for (int i = 0; i < 4; i++) Ws4[t + i * THR] = Wg[t + i * THR];
            __syncthreads();

#pragma unroll
            for (int kk = 0; kk < 32; kk++) {
                int k = kc * 32 + kk;
                float4 w = ((const float4*)(Wvs + kk * C))[cg];
                float4 fa = *(const float4*)&fs[k][p0];
                float4 fb = *(const float4*)&fs[k][p0 + 4];
                float fv[8] = {fa.x, fa.y, fa.z, fa.w, fb.x, fb.y, fb.z, fb.w};
#pragma unroll
                for (int p = 0; p < 8; p++) {
                    acc[0][p] += fv[p] * w.x;
                    acc[1][p] += fv[p] * w.y;
                    acc[2][p] += fv[p] * w.z;
                    acc[3][p] += fv[p] * w.w;
                }
            }
            __syncthreads();
        }

        float4 bias = ((const float4*)bv)[cg];
        float4* gv4 = (float4*)g_value;
#pragma unroll
        for (int p = 0; p < 8; p++) {
            int row = r0 + p0 + p;
            if (row < total) {
                float4 o;
                o.x = acc[0][p] + bias.x;
                o.y = acc[1][p] + bias.y;
                o.z = acc[2][p] + bias.z;
                o.w = acc[3][p] + bias.w;
                gv4[(size_t)row * (C / 4) + cg] = o;
            }
        }
    } else {
        // ================= fill / transpose =================
        float (*tile)[33] = (float(*)[33])smbuf;          // 16.9 KB
        const int vb = blockIdx.x - NV;
        const int n0 = (vb & 4095) * 32, b = vb >> 12;

        {
            const int nl = t >> 5;
            const int c4 = t & 31;
#pragma unroll
            for (int r = 0; r < 4; r++) {
                int n = nl + r * 8;
                float4 v = embed4[((size_t)b * NTOK + n0 + n) * (C / 4) + c4];
                int col = (n + c4) & 31;
                tile[c4 * 4 + 0][col] = v.x;
                tile[c4 * 4 + 1][col] = v.y;
                tile[c4 * 4 + 2][col] = v.z;
                tile[c4 * 4 + 3][col] = v.w;
            }
        }
        __syncthreads();

#pragma unroll
        for (int r = 0; r < 4; r++) {
            int idx = t + r * THR;
            int c = idx >> 3, n4 = idx & 7;
            int rot = c >> 2;
            float4 w;
            w.x = tile[c][(n4 * 4 + 0 + rot) & 31];
            w.y = tile[c][(n4 * 4 + 1 + rot) & 31];
            w.z = tile[c][(n4 * 4 + 2 + rot) & 31];
            w.w = tile[c][(n4 * 4 + 3 + rot) & 31];
            out4[(((size_t)b * C + c) * NTOK + n0) / 4 + n4] = w;
        }
    }
}

// ---------------- K3: deformable attention on compacted tokens ----------------
// dynamic smem layout (45056 B), aliased by phase lifetime:
//   qs   [0, 8192)          phase 1-2 (q vectors)
//   accs [0, 8192)          phase 4-5 (gather output)
//   P    [8192, 26624)      phase 2-4a (proj outputs)
//   sOff [8192, 32768)      phase 4a-4 (int4 corner offsets; overlaps P -> reg-staged)
//   sFx  [32768, 38912)     phase 4a-4 (fp32 x-fraction; disjoint from P)
//   sG   [38912, 45056)     phase 4a-4 (half2 (g0,g1);   disjoint from P)
//   outs [8192, 16384)      phase 5-end
__global__ void __launch_bounds__(THR, 5) k_attn(
    const float* __restrict__ embed, const float* __restrict__ pos,
    const float* __restrict__ refpix,
    const float* __restrict__ Woff, const float* __restrict__ boff,
    const float* __restrict__ Ww, const float* __restrict__ bw,
    const float* __restrict__ Wo, const float* __restrict__ bo,
    const float* __restrict__ ln_g, const float* __restrict__ ln_b,
    float* __restrict__ out)
{
    extern __shared__ float sm[];
    float* qs    = sm;
    float* accs  = sm;
    float* P     = sm + 2048;
    int4*  sOff  = (int4*)(sm + 2048);
    float* sFx   = sm + 8192;
    __half2* sG  = (__half2*)(sm + 9728);
    float* outs  = sm + 2048;

    __shared__ float rpx[TOK], rpy[TOK], s_mu[TOK], s_inv[TOK];
    __shared__ int tok_b[TOK], tok_n[TOK];
    __shared__ int s_cnt, s_tile;

    const int t = threadIdx.x;
    if (t == 0) s_cnt = g_cnt;
    __syncthreads();
    const int cnt = s_cnt;

    for (;;) {
        if (t == 0) s_tile = atomicAdd(&g_tile, 1);
        __syncthreads();
        const int base = s_tile * TOK;
        if (base >= cnt) break;

        if (t < TOK) {
            int id = g_list[min(base + t, cnt - 1)];
            tok_b[t] = id >> 17;
            tok_n[t] = id & (NTOK - 1);
            rpx[t] = refpix[(size_t)id * 2];
            rpy[t] = refpix[(size_t)id * 2 + 1];
        }
        __syncthreads();

        // phase 1: q = embed + pos (float4); 2 tasks/thread
        {
            const float4* e4 = (const float4*)embed;
            const float4* p4 = (const float4*)pos;
            float4* qs4 = (float4*)qs;
#pragma unroll
            for (int s = 0; s < 2; s++) {
                int idx = t + s * THR;                   // < 512
                int tk = idx >> 5, c4 = idx & 31;
                size_t off = ((size_t)tok_b[tk] * NTOK + tok_n[tk]) * (C / 4) + c4;
                float4 e = e4[off], p = p4[off];
                float4 q = {e.x + p.x, e.y + p.y, e.z + p.z, e.w + p.w};
                qs4[idx] = q;
            }
        }
        __syncthreads();

        // phase 2: P = q @ [Woff | Ww] + bias (8-token blocking, k x4)
        for (int it = t; it < NCOL * 2; it += THR) {
            int j = it % NCOL, tg = it / NCOL;
            const float* W; int ld; float bias;
            if (j < NOFF) { W = Woff + j; ld = NOFF; bias = boff[j]; }
            else          { W = Ww + (j - NOFF); ld = NW; bias = bw[j - NOFF]; }
            const float* qrow = qs + tg * 8 * C;
            float acc[8];
#pragma unroll
            for (int tt = 0; tt < 8; tt++) acc[tt] = 0.f;
            for (int k4 = 0; k4 < C / 4; k4++) {
                float w0 = W[(k4 * 4 + 0) * ld];
                float w1 = W[(k4 * 4 + 1) * ld];
                float w2 = W[(k4 * 4 + 2) * ld];
                float w3 = W[(k4 * 4 + 3) * ld];
#pragma unroll
                for (int tt = 0; tt < 8; tt++) {
                    float4 qv = *(const float4*)(qrow + tt * C + k4 * 4);
                    acc[tt] += qv.x * w0 + qv.y * w1 + qv.z * w2 + qv.w * w3;
                }
            }
#pragma unroll
            for (int tt = 0; tt < 8; tt++) P[(tg * 8 + tt) * NCOL + j] = acc[tt] + bias;
        }
        __syncthreads();

        // phase 3: softmax over 12 per (token, head)
        if (t < TOK * HEADS) {
            float* wv = P + (t >> 3) * NCOL + NOFF + (t & 7) * 12;
            float m = wv[0];
#pragma unroll
            for (int i = 1; i < 12; i++) m = fmaxf(m, wv[i]);
            float e[12], s = 0.f;
#pragma unroll
            for (int i = 0; i < 12; i++) { e[i] = expf(wv[i] - m); s += e[i]; }
            float r = 1.f / s;
#pragma unroll
            for (int i = 0; i < 12; i++) wv[i] = e[i] * r;
        }
        __syncthreads();

        // phase 4a: per-sample corner offsets + weights.
        // sFx/sG written directly (disjoint from P); sOff staged in regs (overlaps P).
        {
            int4 ro[6];
#pragma unroll
            for (int s = 0; s < 6; s++) {
                int it = t + s * THR;                    // < 1536
                int tk = it / NW, rem = it % NW;
                int h = rem / 12, lp = rem % 12, l = lp >> 2;
                float wlf = (l == 0) ? (float)W0 : (l == 1) ? (float)W1 : (float)W2;
                float hlf = (l == 0) ? (float)H0 : (l == 1) ? (float)H1 : (float)H2;
                int wl = (l == 0) ? W0 : (l == 1) ? W1 : W2;
                int hh = (l == 0) ? H0 : (l == 1) ? H1 : H2;
                int st = (l == 0) ? 0 : (l == 1) ? S1 : S2;
                int jo = ((h * 3 + l) * 4 + (lp & 3)) * 2;
                float offx = P[tk * NCOL + jo];
                float offy = P[tk * NCOL + jo + 1];
                float a = P[tk * NCOL + NOFF + rem];
                float x = rpx[tk] * wlf + offx - 0.5f;
                float y = rpy[tk] * hlf + offy - 0.5f;
                float x0 = floorf(x), y0 = floorf(y);
                int xi = (int)x0, yi = (int)y0;
                float fy = y - y0;
                sFx[it] = x - x0;
                sG[it] = __floats2half2_rn((1.f - fy) * a, fy * a);

                int vx0 = (xi >= 0) & (xi < wl);
                int vx1 = (xi >= -1) & (xi < wl - 1);
                int vy0 = (yi >= 0) & (yi < hh);
                int vy1 = (yi >= -1) & (yi < hh - 1);
                int xc0 = min(max(xi, 0), wl - 1);
                int xc1 = min(max(xi + 1, 0), wl - 1);
                int yc0 = min(max(yi, 0), hh - 1);
                int yc1 = min(max(yi + 1, 0), hh - 1);
                int pixb = tok_b[tk] * NPIX + st;
                int row0 = pixb + yc0 * wl, row1 = pixb + yc1 * wl;
                ro[s].x = (vx0 & vy0) ? (row0 + xc0) * C : ZPAD;
                ro[s].y = (vx1 & vy0) ? (row0 + xc1) * C : ZPAD;
                ro[s].z = (vx0 & vy1) ? (row1 + xc0) * C : ZPAD;
                ro[s].w = (vx1 & vy1) ? (row1 + xc1) * C : ZPAD;
            }
            __syncthreads();     // all P reads done; safe to overwrite P with sOff
#pragma unroll
            for (int s = 0; s < 6; s++) sOff[t + s * THR] = ro[s];
        }
        __syncthreads();

        // phase 4: bilinear gather + accumulate (thread owns channel c for 8 tokens)
        {
            const int c = t & 127, tg = t >> 7, h12 = ((t & 127) >> 4) * 12;
            for (int tt = 0; tt < 8; tt++) {
                int tk = tg * 8 + tt;
                int sbase = tk * NW + h12;
                float acc = 0.f;
#pragma unroll
                for (int lp = 0; lp < 12; lp++) {
                    int4 o = sOff[sbase + lp];
                    float fx = sFx[sbase + lp];
                    float2 g = __half22float2(sG[sbase + lp]);
                    float v00 = g_value[o.x + c];
                    float v10 = g_value[o.y + c];
                    float v01 = g_value[o.z + c];
                    float v11 = g_value[o.w + c];
                    float wx0 = 1.f - fx;
                    acc += (v00 * wx0 + v10 * fx) * g.x + (v01 * wx0 + v11 * fx) * g.y;
                }
                accs[tk * C + c] = acc;
            }
        }
        __syncthreads();

        // phase 5: out = accs @ Wo + bo + identity(re-read) (8-token blocking, k x4)
        {
            const int c = t & 127, tg = t >> 7;
            const float* arow = accs + tg * 8 * C;
            float o[8];
#pragma unroll
            for (int tt = 0; tt < 8; tt++) o[tt] = 0.f;
            for (int k4 = 0; k4 < C / 4; k4++) {
                float w0 = Wo[(k4 * 4 + 0) * C + c];
                float w1 = Wo[(k4 * 4 + 1) * C + c];
                float w2 = Wo[(k4 * 4 + 2) * C + c];
                float w3 = Wo[(k4 * 4 + 3) * C + c];
#pragma unroll
                for (int tt = 0; tt < 8; tt++) {
                    float4 av = *(const float4*)(arow + tt * C + k4 * 4);
                    o[tt] += av.x * w0 + av.y * w1 + av.z * w2 + av.w * w3;
                }
            }
            float bias = bo[c];
#pragma unroll
            for (int tt = 0; tt < 8; tt++) {
                int tk = tg * 8 + tt;
                float id = embed[((size_t)tok_b[tk] * NTOK + tok_n[tk]) * C + c];
                outs[tk * C + c] = o[tt] + bias + id;
            }
        }
        __syncthreads();

        // LayerNorm stats: warp per token, shuffle reduce (8 warps x 2 tokens)
        {
            int w0id = t >> 5, lane = t & 31;
            for (int w = w0id; w < TOK; w += 8) {
                float v0 = outs[w * C + lane];
                float v1 = outs[w * C + lane + 32];
                float v2 = outs[w * C + lane + 64];
                float v3 = outs[w * C + lane + 96];
                float s = v0 + v1 + v2 + v3;
                float s2 = v0 * v0 + v1 * v1 + v2 * v2 + v3 * v3;
#pragma unroll
                for (int d = 16; d > 0; d >>= 1) {
                    s  += __shfl_xor_sync(0xffffffff, s, d);
                    s2 += __shfl_xor_sync(0xffffffff, s2, d);
                }
                if (lane == 0) {
                    float mu = s * (1.f / C);
                    float var = s2 * (1.f / C) - mu * mu;
                    s_mu[w] = mu;
                    s_inv[w] = rsqrtf(var + 1e-5f);
                }
            }
        }
        __syncthreads();

        // normalized scatter-write into transposed output
        int nt = min(TOK, cnt - base);
        for (int idx = t; idx < nt * C; idx += THR) {
            int tk = idx >> 7, cc = idx & 127;
            float v = (outs[tk * C + cc] - s_mu[tk]) * s_inv[tk] * ln_g[cc] + ln_b[cc];
            out[((size_t)tok_b[tk] * C + cc) * NTOK + tok_n[tk]] = v;
        }
        __syncthreads();   // protect smem reuse for next tile
    }
}

// ---------------- launcher ----------------
extern "C" void kernel_launch(void* const* d_in, const int* in_sizes, int n_in,
                              void* d_out, int out_size)
{
    // bind inputs by element count (robust to metadata ordering)
    const float *embed = 0, *pos = 0, *refpix = 0;
    const float *f0 = 0, *f1 = 0, *f2 = 0;
    const float *Wv = 0, *bv = 0, *Woff = 0, *boff = 0, *Ww = 0, *bw = 0;
    const float *Wo = 0, *bo = 0, *lng = 0, *lnb = 0;
    const int* vol = 0;
    int seen_big = 0, seen_16384 = 0, seen_128 = 0;
    for (int i = 0; i < n_in; i++) {
        int s = in_sizes[i];
        const float* p = (const float*)d_in[i];
        switch (s) {
            case 33554432: if (seen_big++ == 0) embed = p; else pos = p; break;
            case 786432:   vol = (const int*)d_in[i]; break;
            case 524288:   refpix = p; break;
            case 1840896:  f0 = p; break;
            case 473088:   f1 = p; break;
            case 119808:   f2 = p; break;
            case 16384:    if (seen_16384++ == 0) Wv = p; else Wo = p; break;
            case 24576:    Woff = p; break;
            case 192:      boff = p; break;
            case 12288:    Ww = p; break;
            case 96:       bw = p; break;
            case 128: {
                int k = seen_128++;
                if (k == 0) bv = p; else if (k == 1) bo = p;
                else if (k == 2) lng = p; else lnb = p;
                break;
            }
            default: break;
        }
    }
    float* out = (float*)d_out;

    const int FV_SMEM = 49152;    // value blocks: 48KB; fill blocks use subset
    const int AT_SMEM = 45056;    // see layout comment on k_attn
    cudaFuncSetAttribute(k_fillvalue, cudaFuncAttributeMaxDynamicSharedMemorySize, FV_SMEM);
    cudaFuncSetAttribute(k_attn, cudaFuncAttributeMaxDynamicSharedMemorySize, AT_SMEM);

    k_zero<<<BB * NTOK / (4 * 256), 256>>>();
    k_fillvalue<<<NV + NFILL + NSCAT, THR, FV_SMEM>>>(
        (const float4*)embed, (float4*)out, f0, f1, f2, Wv, bv, vol);
    k_attn<<<5 * 148, THR, AT_SMEM>>>(embed, pos, refpix, Woff, boff, Ww, bw,
                                      Wo, bo, lng, lnb, out);
}

// round 13
// speedup vs baseline: 1.0514x; 1.0514x over previous
#include <cuda_runtime.h>
#include <cuda_fp16.h>
#include <stdint.h>

#define XD 128
#define YD 128
#define ZD 8
#define NTOK 131072          // XD*YD*ZD
#define BB 2
#define C 128
#define HEADS 8
#define LEVELS 3
#define POINTS 4
#define NOFF 192             // HEADS*LEVELS*POINTS*2
#define NW 96                // HEADS*LEVELS*POINTS
#define NCOL 288             // NOFF+NW
#define NPIX 9507
#define H0 47
#define W0 153
#define H1 24
#define W1 77
#define H2 12
#define W2 39
#define S1 7191              // H0*W0
#define S2 9039              // S1 + H1*W1

#define TOK 16
#define THR 256
#define NV 298               // ceil(BB*NPIX / 64) value blocks in fused kernel
#define NFILL 8192           // (NTOK/32)*BB fill blocks
#define NSCAT 1024           // scatter blocks (BB*NTOK/256)
#define ZPIX (BB * NPIX)     // pixel index of the permanently-zero pad row

// ---------------- scratch (static device globals; no allocation) ----------------
__device__ float g_value[((size_t)BB * NPIX + 1) * C]; // +1 row: zero pad (never written)
__device__ int g_mask[BB * NTOK];
__device__ int g_list[BB * NTOK];
__device__ int g_cnt;
__device__ int g_tile;

// ---------------- K1: zero mask + counters ----------------
__global__ void k_zero() {
    int i = blockIdx.x * blockDim.x + threadIdx.x;   // 65536 threads x int4
    ((int4*)g_mask)[i] = make_int4(0, 0, 0, 0);
    if (i == 0) { g_cnt = 0; g_tile = 0; }
}

// ---------------- K2 (fused): value projection + fill/transpose + scatter/compact ----------------
__global__ void __launch_bounds__(THR) k_fillvalue(
    const float4* __restrict__ embed4, float4* __restrict__ out4,
    const float* __restrict__ f0, const float* __restrict__ f1, const float* __restrict__ f2,
    const float* __restrict__ Wv, const float* __restrict__ bv,
    const int* __restrict__ vol)
{
    extern __shared__ __align__(16) char smbuf[];
    const int t = threadIdx.x;

    if (blockIdx.x >= NV + NFILL) {
        // ================= scatter + compact =================
        int i = (blockIdx.x - NV - NFILL) * THR + t;
        int x = vol[3 * i], y = vol[3 * i + 1], z = vol[3 * i + 2];
        if ((unsigned)x < XD && (unsigned)y < YD && (unsigned)z < ZD) {
            int b = i >> 17;
            int v = b * NTOK + x * (YD * ZD) + y * ZD + z;
            if (atomicExch(&g_mask[v], 1) == 0) {
                int p = atomicAdd(&g_cnt, 1);
                g_list[p] = v;
            }
        }
        return;
    }

    if (blockIdx.x < NV) {
        // ================= value projection =================
        float (*fs)[64] = (float(*)[64])smbuf;            // 32 KB
        float* Wvs = (float*)(smbuf + 32768);             // 16 KB: [32][128]
        __shared__ const float* ptrs[64];
        __shared__ int strd[64];
        const int r0 = blockIdx.x * 64;
        const int total = BB * NPIX;

        if (t < 64) {
            int row = r0 + t;
            if (row < total) {
                int b = row / NPIX, pix = row % NPIX;
                const float* f; int HW, hw;
                if (pix < S1)      { f = f0; HW = H0 * W0; hw = pix; }
                else if (pix < S2) { f = f1; HW = H1 * W1; hw = pix - S1; }
                else               { f = f2; HW = H2 * W2; hw = pix - S2; }
                ptrs[t] = f + (size_t)b * C * HW + hw;
                strd[t] = HW;
            } else { ptrs[t] = f0; strd[t] = 0; }
        }
        __syncthreads();

#pragma unroll
        for (int i = 0; i < 32; i++) {                    // C*64/THR = 32 loads/thread
            int idx = t + i * THR;
            int k = idx >> 6, j = idx & 63;
            fs[k][j] = ptrs[j][(size_t)k * strd[j]];
        }
        __syncthreads();

        const int cg = t & 31;                            // float4 channel group
        const int p0 = (t >> 5) * 8;                      // 8 pixels
        float acc[4][8];
#pragma unroll
        for (int ci = 0; ci < 4; ci++)
#pragma unroll
            for (int p = 0; p < 8; p++) acc[ci][p] = 0.f;

        for (int kc = 0; kc < 4; kc++) {
            const float4* Wg = (const float4*)(Wv + kc * 32 * C);
            float4* Ws4 = (float4*)Wvs;
#pragma unroll
            for (int i = 0; i < 4; i++) Ws4[t + i * THR] = Wg[t + i * THR];
            __syncthreads();

#pragma unroll
            for (int kk = 0; kk < 32; kk++) {
                int k = kc * 32 + kk;
                float4 w = ((const float4*)(Wvs + kk * C))[cg];
                float4 fa = *(const float4*)&fs[k][p0];
                float4 fb = *(const float4*)&fs[k][p0 + 4];
                float fv[8] = {fa.x, fa.y, fa.z, fa.w, fb.x, fb.y, fb.z, fb.w};
#pragma unroll
                for (int p = 0; p < 8; p++) {
                    acc[0][p] += fv[p] * w.x;
                    acc[1][p] += fv[p] * w.y;
                    acc[2][p] += fv[p] * w.z;
                    acc[3][p] += fv[p] * w.w;
                }
            }
            __syncthreads();
        }

        float4 bias = ((const float4*)bv)[cg];
        float4* gv4 = (float4*)g_value;
#pragma unroll
        for (int p = 0; p < 8; p++) {
            int row = r0 + p0 + p;
            if (row < total) {
                float4 o;
                o.x = acc[0][p] + bias.x;
                o.y = acc[1][p] + bias.y;
                o.z = acc[2][p] + bias.z;
                o.w = acc[3][p] + bias.w;
                gv4[(size_t)row * (C / 4) + cg] = o;
            }
        }
    } else {
        // ================= fill / transpose =================
        float (*tile)[33] = (float(*)[33])smbuf;          // 16.9 KB
        const int vb = blockIdx.x - NV;
        const int n0 = (vb & 4095) * 32, b = vb >> 12;

        {
            const int nl = t >> 5;
            const int c4 = t & 31;
#pragma unroll
            for (int r = 0; r < 4; r++) {
                int n = nl + r * 8;
                float4 v = embed4[((size_t)b * NTOK + n0 + n) * (C / 4) + c4];
                int col = (n + c4) & 31;
                tile[c4 * 4 + 0][col] = v.x;
                tile[c4 * 4 + 1][col] = v.y;
                tile[c4 * 4 + 2][col] = v.z;
                tile[c4 * 4 + 3][col] = v.w;
            }
        }
        __syncthreads();

#pragma unroll
        for (int r = 0; r < 4; r++) {
            int idx = t + r * THR;
            int c = idx >> 3, n4 = idx & 7;
            int rot = c >> 2;
            float4 w;
            w.x = tile[c][(n4 * 4 + 0 + rot) & 31];
            w.y = tile[c][(n4 * 4 + 1 + rot) & 31];
            w.z = tile[c][(n4 * 4 + 2 + rot) & 31];
            w.w = tile[c][(n4 * 4 + 3 + rot) & 31];
            out4[(((size_t)b * C + c) * NTOK + n0) / 4 + n4] = w;
        }
    }
}

// ---------------- K3: deformable attention on compacted tokens ----------------
// dynamic smem (51200 B), DISJOINT regions (no reg staging, no spills):
//   qs/accs/outs [0, 2048) floats       (phase-lifetime reuse, never concurrent)
//   P            [2048, 6656) floats    proj outputs (dead after 4a)
//   sC           [6656, 9728) floats    ushort4 corner pixel indices (12 KB)
//   sW0          [9728, 11264) floats   half2 (w00, w10) (6 KB)
//   sW1          [11264, 12800) floats  half2 (w01, w11) (6 KB)
__global__ void __launch_bounds__(THR, 4) k_attn(
    const float* __restrict__ embed, const float* __restrict__ pos,
    const float* __restrict__ refpix,
    const float* __restrict__ Woff, const float* __restrict__ boff,
    const float* __restrict__ Ww, const float* __restrict__ bw,
    const float* __restrict__ Wo, const float* __restrict__ bo,
    const float* __restrict__ ln_g, const float* __restrict__ ln_b,
    float* __restrict__ out)
{
    extern __shared__ float sm[];
    float* qs     = sm;
    float* accs   = sm;
    float* outs   = sm + 2048;        // overlaps P (P dead by phase 5)
    float* P      = sm + 2048;
    ushort4* sC   = (ushort4*)(sm + 6656);
    __half2* sW0  = (__half2*)(sm + 9728);
    __half2* sW1  = (__half2*)(sm + 11264);

    __shared__ float rpx[TOK], rpy[TOK], s_mu[TOK], s_inv[TOK];
    __shared__ int tok_b[TOK], tok_n[TOK];
    __shared__ int s_cnt, s_tile;

    const int t = threadIdx.x;
    if (t == 0) s_cnt = g_cnt;
    __syncthreads();
    const int cnt = s_cnt;

    for (;;) {
        if (t == 0) s_tile = atomicAdd(&g_tile, 1);
        __syncthreads();
        const int base = s_tile * TOK;
        if (base >= cnt) break;

        if (t < TOK) {
            int id = g_list[min(base + t, cnt - 1)];
            tok_b[t] = id >> 17;
            tok_n[t] = id & (NTOK - 1);
            rpx[t] = refpix[(size_t)id * 2];
            rpy[t] = refpix[(size_t)id * 2 + 1];
        }
        __syncthreads();

        // phase 1: q = embed + pos (float4); 2 tasks/thread
        {
            const float4* e4 = (const float4*)embed;
            const float4* p4 = (const float4*)pos;
            float4* qs4 = (float4*)qs;
#pragma unroll
            for (int s = 0; s < 2; s++) {
                int idx = t + s * THR;                   // < 512
                int tk = idx >> 5, c4 = idx & 31;
                size_t off = ((size_t)tok_b[tk] * NTOK + tok_n[tk]) * (C / 4) + c4;
                float4 e = e4[off], p = p4[off];
                float4 q = {e.x + p.x, e.y + p.y, e.z + p.z, e.w + p.w};
                qs4[idx] = q;
            }
        }
        __syncthreads();

        // phase 2: P = q @ [Woff | Ww] + bias (8-token blocking, k x4)
        for (int it = t; it < NCOL * 2; it += THR) {
            int j = it % NCOL, tg = it / NCOL;
            const float* W; int ld; float bias;
            if (j < NOFF) { W = Woff + j; ld = NOFF; bias = boff[j]; }
            else          { W = Ww + (j - NOFF); ld = NW; bias = bw[j - NOFF]; }
            const float* qrow = qs + tg * 8 * C;
            float acc[8];
#pragma unroll
            for (int tt = 0; tt < 8; tt++) acc[tt] = 0.f;
            for (int k4 = 0; k4 < C / 4; k4++) {
                float w0 = W[(k4 * 4 + 0) * ld];
                float w1 = W[(k4 * 4 + 1) * ld];
                float w2 = W[(k4 * 4 + 2) * ld];
                float w3 = W[(k4 * 4 + 3) * ld];
#pragma unroll
                for (int tt = 0; tt < 8; tt++) {
                    float4 qv = *(const float4*)(qrow + tt * C + k4 * 4);
                    acc[tt] += qv.x * w0 + qv.y * w1 + qv.z * w2 + qv.w * w3;
                }
            }
#pragma unroll
            for (int tt = 0; tt < 8; tt++) P[(tg * 8 + tt) * NCOL + j] = acc[tt] + bias;
        }
        __syncthreads();

        // phase 3: softmax over 12 per (token, head)
        if (t < TOK * HEADS) {
            float* wv = P + (t >> 3) * NCOL + NOFF + (t & 7) * 12;
            float m = wv[0];
#pragma unroll
            for (int i = 1; i < 12; i++) m = fmaxf(m, wv[i]);
            float e[12], s = 0.f;
#pragma unroll
            for (int i = 0; i < 12; i++) { e[i] = expf(wv[i] - m); s += e[i]; }
            float r = 1.f / s;
#pragma unroll
            for (int i = 0; i < 12; i++) wv[i] = e[i] * r;
        }
        __syncthreads();

        // phase 4a: per-sample corner pixel indices + 4 half corner weights.
        // Writes go to sC/sW0/sW1 (disjoint from P) — no staging needed.
#pragma unroll
        for (int s = 0; s < 6; s++) {
            int it = t + s * THR;                        // < 1536
            int tk = it / NW, rem = it % NW;
            int h = rem / 12, lp = rem % 12, l = lp >> 2;
            float wlf = (l == 0) ? (float)W0 : (l == 1) ? (float)W1 : (float)W2;
            float hlf = (l == 0) ? (float)H0 : (l == 1) ? (float)H1 : (float)H2;
            int wl = (l == 0) ? W0 : (l == 1) ? W1 : W2;
            int hh = (l == 0) ? H0 : (l == 1) ? H1 : H2;
            int st = (l == 0) ? 0 : (l == 1) ? S1 : S2;
            int jo = ((h * 3 + l) * 4 + (lp & 3)) * 2;
            float offx = P[tk * NCOL + jo];
            float offy = P[tk * NCOL + jo + 1];
            float a = P[tk * NCOL + NOFF + rem];
            float x = rpx[tk] * wlf + offx - 0.5f;
            float y = rpy[tk] * hlf + offy - 0.5f;
            float x0 = floorf(x), y0 = floorf(y);
            int xi = (int)x0, yi = (int)y0;
            float fx = x - x0, fy = y - y0;
            float g0 = (1.f - fy) * a, g1 = fy * a;

            int vx0 = (xi >= 0) & (xi < wl);
            int vx1 = (xi >= -1) & (xi < wl - 1);
            int vy0 = (yi >= 0) & (yi < hh);
            int vy1 = (yi >= -1) & (yi < hh - 1);
            int xc0 = min(max(xi, 0), wl - 1);
            int xc1 = min(max(xi + 1, 0), wl - 1);
            int yc0 = min(max(yi, 0), hh - 1);
            int yc1 = min(max(yi + 1, 0), hh - 1);
            int pixb = tok_b[tk] * NPIX + st;
            int row0 = pixb + yc0 * wl, row1 = pixb + yc1 * wl;
            ushort4 cidx;
            cidx.x = (unsigned short)((vx0 & vy0) ? (row0 + xc0) : ZPIX);
            cidx.y = (unsigned short)((vx1 & vy0) ? (row0 + xc1) : ZPIX);
            cidx.z = (unsigned short)((vx0 & vy1) ? (row1 + xc0) : ZPIX);
            cidx.w = (unsigned short)((vx1 & vy1) ? (row1 + xc1) : ZPIX);
            sC[it] = cidx;
            float wx0 = 1.f - fx;
            sW0[it] = __floats2half2_rn(wx0 * g0, fx * g0);
            sW1[it] = __floats2half2_rn(wx0 * g1, fx * g1);
        }
        __syncthreads();

        // phase 4: bilinear gather + accumulate (thread owns channel c for 8 tokens)
        {
            const int c = t & 127, tg = t >> 7, h12 = ((t & 127) >> 4) * 12;
            for (int tt = 0; tt < 8; tt++) {
                int tk = tg * 8 + tt;
                int sbase = tk * NW + h12;
                float acc = 0.f;
#pragma unroll
                for (int lp = 0; lp < 12; lp++) {
                    ushort4 px = sC[sbase + lp];
                    float2 ga = __half22float2(sW0[sbase + lp]);
                    float2 gb = __half22float2(sW1[sbase + lp]);
                    float v00 = g_value[((int)px.x << 7) + c];
                    float v10 = g_value[((int)px.y << 7) + c];
                    float v01 = g_value[((int)px.z << 7) + c];
                    float v11 = g_value[((int)px.w << 7) + c];
                    acc += v00 * ga.x + v10 * ga.y + v01 * gb.x + v11 * gb.y;
                }
                accs[tk * C + c] = acc;
            }
        }
        __syncthreads();

        // phase 5: out = accs @ Wo + bo + identity(re-read) (8-token blocking, k x4)
        {
            const int c = t & 127, tg = t >> 7;
            const float* arow = accs + tg * 8 * C;
            float o[8];
#pragma unroll
            for (int tt = 0; tt < 8; tt++) o[tt] = 0.f;
            for (int k4 = 0; k4 < C / 4; k4++) {
                float w0 = Wo[(k4 * 4 + 0) * C + c];
                float w1 = Wo[(k4 * 4 + 1) * C + c];
                float w2 = Wo[(k4 * 4 + 2) * C + c];
                float w3 = Wo[(k4 * 4 + 3) * C + c];
#pragma unroll
                for (int tt = 0; tt < 8; tt++) {
                    float4 av = *(const float4*)(arow + tt * C + k4 * 4);
                    o[tt] += av.x * w0 + av.y * w1 + av.z * w2 + av.w * w3;
                }
            }
            float bias = bo[c];
#pragma unroll
            for (int tt = 0; tt < 8; tt++) {
                int tk = tg * 8 + tt;
                float id = embed[((size_t)tok_b[tk] * NTOK + tok_n[tk]) * C + c];
                outs[tk * C + c] = o[tt] + bias + id;
            }
        }
        __syncthreads();

        // LayerNorm stats: warp per token, shuffle reduce (8 warps x 2 tokens)
        {
            int w0id = t >> 5, lane = t & 31;
            for (int w = w0id; w < TOK; w += 8) {
                float v0 = outs[w * C + lane];
                float v1 = outs[w * C + lane + 32];
                float v2 = outs[w * C + lane + 64];
                float v3 = outs[w * C + lane + 96];
                float s = v0 + v1 + v2 + v3;
                float s2 = v0 * v0 + v1 * v1 + v2 * v2 + v3 * v3;
#pragma unroll
                for (int d = 16; d > 0; d >>= 1) {
                    s  += __shfl_xor_sync(0xffffffff, s, d);
                    s2 += __shfl_xor_sync(0xffffffff, s2, d);
                }
                if (lane == 0) {
                    float mu = s * (1.f / C);
                    float var = s2 * (1.f / C) - mu * mu;
                    s_mu[w] = mu;
                    s_inv[w] = rsqrtf(var + 1e-5f);
                }
            }
        }
        __syncthreads();

        // normalized scatter-write into transposed output
        int nt = min(TOK, cnt - base);
        for (int idx = t; idx < nt * C; idx += THR) {
            int tk = idx >> 7, cc = idx & 127;
            float v = (outs[tk * C + cc] - s_mu[tk]) * s_inv[tk] * ln_g[cc] + ln_b[cc];
            out[((size_t)tok_b[tk] * C + cc) * NTOK + tok_n[tk]] = v;
        }
        __syncthreads();   // protect smem reuse for next tile
    }
}

// ---------------- launcher ----------------
extern "C" void kernel_launch(void* const* d_in, const int* in_sizes, int n_in,
                              void* d_out, int out_size)
{
    // bind inputs by element count (robust to metadata ordering)
    const float *embed = 0, *pos = 0, *refpix = 0;
    const float *f0 = 0, *f1 = 0, *f2 = 0;
    const float *Wv = 0, *bv = 0, *Woff = 0, *boff = 0, *Ww = 0, *bw = 0;
    const float *Wo = 0, *bo = 0, *lng = 0, *lnb = 0;
    const int* vol = 0;
    int seen_big = 0, seen_16384 = 0, seen_128 = 0;
    for (int i = 0; i < n_in; i++) {
        int s = in_sizes[i];
        const float* p = (const float*)d_in[i];
        switch (s) {
            case 33554432: if (seen_big++ == 0) embed = p; else pos = p; break;
            case 786432:   vol = (const int*)d_in[i]; break;
            case 524288:   refpix = p; break;
            case 1840896:  f0 = p; break;
            case 473088:   f1 = p; break;
            case 119808:   f2 = p; break;
            case 16384:    if (seen_16384++ == 0) Wv = p; else Wo = p; break;
            case 24576:    Woff = p; break;
            case 192:      boff = p; break;
            case 12288:    Ww = p; break;
            case 96:       bw = p; break;
            case 128: {
                int k = seen_128++;
                if (k == 0) bv = p; else if (k == 1) bo = p;
                else if (k == 2) lng = p; else lnb = p;
                break;
            }
            default: break;
        }
    }
    float* out = (float*)d_out;

    const int FV_SMEM = 49152;    // value blocks: 48KB; fill/scatter use subset
    const int AT_SMEM = 51200;    // see layout comment on k_attn
    cudaFuncSetAttribute(k_fillvalue, cudaFuncAttributeMaxDynamicSharedMemorySize, FV_SMEM);
    cudaFuncSetAttribute(k_attn, cudaFuncAttributeMaxDynamicSharedMemorySize, AT_SMEM);

    k_zero<<<BB * NTOK / (4 * 256), 256>>>();
    k_fillvalue<<<NV + NFILL + NSCAT, THR, FV_SMEM>>>(
        (const float4*)embed, (float4*)out, f0, f1, f2, Wv, bv, vol);
    k_attn<<<4 * 148, THR, AT_SMEM>>>(embed, pos, refpix, Woff, boff, Ww, bw,
                                      Wo, bo, lng, lnb, out);
}

// round 14
// speedup vs baseline: 1.1357x; 1.0801x over previous
#include <cuda_runtime.h>
#include <stdint.h>

#define XD 128
#define YD 128
#define ZD 8
#define NTOK 131072          // XD*YD*ZD
#define BB 2
#define C 128
#define HEADS 8
#define LEVELS 3
#define POINTS 4
#define NOFF 192             // HEADS*LEVELS*POINTS*2
#define NW 96                // HEADS*LEVELS*POINTS
#define NCOL 288             // NOFF+NW
#define NPIX 9507
#define H0 47
#define W0 153
#define H1 24
#define W1 77
#define H2 12
#define W2 39
#define S1 7191              // H0*W0
#define S2 9039              // S1 + H1*W1

#define TOK 16
#define THR 256
#define NV 298               // value blocks in k_prep
#define NSCAT 1024           // scatter blocks in k_prep
#define NATTN 740            // persistent attn blocks (5 blocks/SM x 148)
#define NFILL 8192           // fill blocks ((NTOK/32)*BB)

// ---------------- scratch (static device globals; no allocation) ----------------
__device__ float g_value[(size_t)BB * NPIX * C];
__device__ int g_mask[BB * NTOK];
__device__ int g_list[BB * NTOK];
__device__ int g_cnt;

// ---------------- K1: zero mask + counter ----------------
__global__ void k_zero() {
    int i = blockIdx.x * blockDim.x + threadIdx.x;   // 65536 threads x int4
    ((int4*)g_mask)[i] = make_int4(0, 0, 0, 0);
    if (i == 0) g_cnt = 0;
}

// ---------------- K2 (fused prep): value projection + scatter/compact ----------------
// blocks [0, NV): value projection, 64 px/block, Wv cached in smem in 32-k chunks
// blocks [NV, NV+NSCAT): scatter vol_pts -> mask -> compact list
__global__ void __launch_bounds__(THR) k_prep(
    const float* __restrict__ f0, const float* __restrict__ f1, const float* __restrict__ f2,
    const float* __restrict__ Wv, const float* __restrict__ bv,
    const int* __restrict__ vol)
{
    extern __shared__ __align__(16) char smbuf[];
    const int t = threadIdx.x;

    if (blockIdx.x >= NV) {
        // ================= scatter + compact =================
        int i = (blockIdx.x - NV) * THR + t;
        int x = vol[3 * i], y = vol[3 * i + 1], z = vol[3 * i + 2];
        if ((unsigned)x < XD && (unsigned)y < YD && (unsigned)z < ZD) {
            int b = i >> 17;
            int v = b * NTOK + x * (YD * ZD) + y * ZD + z;
            if (atomicExch(&g_mask[v], 1) == 0) {
                int p = atomicAdd(&g_cnt, 1);
                g_list[p] = v;
            }
        }
        return;
    }

    // ================= value projection =================
    float (*fs)[64] = (float(*)[64])smbuf;            // 32 KB
    float* Wvs = (float*)(smbuf + 32768);             // 16 KB: [32][128]
    __shared__ const float* ptrs[64];
    __shared__ int strd[64];
    const int r0 = blockIdx.x * 64;
    const int total = BB * NPIX;

    if (t < 64) {
        int row = r0 + t;
        if (row < total) {
            int b = row / NPIX, pix = row % NPIX;
            const float* f; int HW, hw;
            if (pix < S1)      { f = f0; HW = H0 * W0; hw = pix; }
            else if (pix < S2) { f = f1; HW = H1 * W1; hw = pix - S1; }
            else               { f = f2; HW = H2 * W2; hw = pix - S2; }
            ptrs[t] = f + (size_t)b * C * HW + hw;
            strd[t] = HW;
        } else { ptrs[t] = f0; strd[t] = 0; }
    }
    __syncthreads();

#pragma unroll
    for (int i = 0; i < 32; i++) {                    // C*64/THR = 32 loads/thread
        int idx = t + i * THR;
        int k = idx >> 6, j = idx & 63;
        fs[k][j] = ptrs[j][(size_t)k * strd[j]];
    }
    __syncthreads();

    const int cg = t & 31;                            // float4 channel group
    const int p0 = (t >> 5) * 8;                      // 8 pixels
    float acc[4][8];
#pragma unroll
    for (int ci = 0; ci < 4; ci++)
#pragma unroll
        for (int p = 0; p < 8; p++) acc[ci][p] = 0.f;

    for (int kc = 0; kc < 4; kc++) {
        const float4* Wg = (const float4*)(Wv + kc * 32 * C);
        float4* Ws4 = (float4*)Wvs;
#pragma unroll
        for (int i = 0; i < 4; i++) Ws4[t + i * THR] = Wg[t + i * THR];
        __syncthreads();

#pragma unroll
        for (int kk = 0; kk < 32; kk++) {
            int k = kc * 32 + kk;
            float4 w = ((const float4*)(Wvs + kk * C))[cg];
            float4 fa = *(const float4*)&fs[k][p0];
            float4 fb = *(const float4*)&fs[k][p0 + 4];
            float fv[8] = {fa.x, fa.y, fa.z, fa.w, fb.x, fb.y, fb.z, fb.w};
#pragma unroll
            for (int p = 0; p < 8; p++) {
                acc[0][p] += fv[p] * w.x;
                acc[1][p] += fv[p] * w.y;
                acc[2][p] += fv[p] * w.z;
                acc[3][p] += fv[p] * w.w;
            }
        }
        __syncthreads();
    }

    float4 bias = ((const float4*)bv)[cg];
    float4* gv4 = (float4*)g_value;
#pragma unroll
    for (int p = 0; p < 8; p++) {
        int row = r0 + p0 + p;
        if (row < total) {
            float4 o;
            o.x = acc[0][p] + bias.x;
            o.y = acc[1][p] + bias.y;
            o.z = acc[2][p] + bias.z;
            o.w = acc[3][p] + bias.w;
            gv4[(size_t)row * (C / 4) + cg] = o;
        }
    }
}

// ---------------- K3 (merged): attn blocks [0,NATTN) + mask-aware fill blocks ----------------
// attn and fill write DISJOINT output columns (mask==1 -> attn, mask==0 -> fill),
// so they can share one launch; attn (ALU/issue-bound) overlaps fill (DRAM-bound).
// dynamic smem 34816 B; attn statics ~6.7 KB -> 5 blocks/SM.
__global__ void __launch_bounds__(THR, 5) k_main(
    const float* __restrict__ embed, const float* __restrict__ pos,
    const float* __restrict__ refpix,
    const float* __restrict__ Woff, const float* __restrict__ boff,
    const float* __restrict__ Ww, const float* __restrict__ bw,
    const float* __restrict__ Wo, const float* __restrict__ bo,
    const float* __restrict__ ln_g, const float* __restrict__ ln_b,
    float* __restrict__ out)
{
    extern __shared__ float sm[];
    const int t = threadIdx.x;

    if (blockIdx.x >= NATTN) {
        // ================= mask-aware fill / transpose =================
        float (*tile)[33] = (float(*)[33])sm;         // 16.9 KB of the 34 KB
        __shared__ int smask[32];
        const int vb = blockIdx.x - NATTN;
        const int n0 = (vb & 4095) * 32, b = vb >> 12;
        const float4* embed4 = (const float4*)embed;
        float4* out4 = (float4*)out;

        if (t < 32) smask[t] = g_mask[b * NTOK + n0 + t];
        {
            const int nl = t >> 5;
            const int c4 = t & 31;
#pragma unroll
            for (int r = 0; r < 4; r++) {
                int n = nl + r * 8;
                float4 v = embed4[((size_t)b * NTOK + n0 + n) * (C / 4) + c4];
                int col = (n + c4) & 31;
                tile[c4 * 4 + 0][col] = v.x;
                tile[c4 * 4 + 1][col] = v.y;
                tile[c4 * 4 + 2][col] = v.z;
                tile[c4 * 4 + 3][col] = v.w;
            }
        }
        __syncthreads();

#pragma unroll
        for (int r = 0; r < 4; r++) {
            int idx = t + r * THR;
            int c = idx >> 3, n4 = idx & 7;
            int rot = c >> 2;
            float4 w;
            w.x = tile[c][(n4 * 4 + 0 + rot) & 31];
            w.y = tile[c][(n4 * 4 + 1 + rot) & 31];
            w.z = tile[c][(n4 * 4 + 2 + rot) & 31];
            w.w = tile[c][(n4 * 4 + 3 + rot) & 31];
            int m0 = smask[n4 * 4 + 0], m1 = smask[n4 * 4 + 1];
            int m2 = smask[n4 * 4 + 2], m3 = smask[n4 * 4 + 3];
            if ((m0 | m1 | m2 | m3) == 0) {
                out4[(((size_t)b * C + c) * NTOK + n0) / 4 + n4] = w;
            } else {
                float* op = out + ((size_t)b * C + c) * NTOK + n0 + n4 * 4;
                if (!m0) op[0] = w.x;
                if (!m1) op[1] = w.y;
                if (!m2) op[2] = w.z;
                if (!m3) op[3] = w.w;
            }
        }
        return;
    }

    // ================= deformable attention (R8-verbatim body) =================
    float* qs    = sm;                        // TOK*C      (reused as accs)
    float* es    = qs + TOK * C;              // TOK*C
    float* P     = es + TOK * C;              // TOK*NCOL   (reused as outs)
    float* spF   = P;                         // aliases over dead P
    float* spG0  = P + 1536;
    float* spG1  = P + 3072;
    float* accs  = qs;
    float* outs  = P;

    __shared__ int sp_xy[TOK * NW];           // 6144 B static
    __shared__ float rpx[TOK], rpy[TOK], s_mu[TOK], s_inv[TOK];
    __shared__ int tok_b[TOK], tok_n[TOK];
    __shared__ int s_cnt;

    if (t == 0) s_cnt = g_cnt;
    __syncthreads();
    const int cnt = s_cnt;

    for (int tile = blockIdx.x; tile * TOK < cnt; tile += NATTN) {
        const int base = tile * TOK;

        if (t < TOK) {
            int id = g_list[min(base + t, cnt - 1)];
            tok_b[t] = id >> 17;
            tok_n[t] = id & (NTOK - 1);
            rpx[t] = refpix[(size_t)id * 2];
            rpy[t] = refpix[(size_t)id * 2 + 1];
        }
        __syncthreads();

        // phase 1: q = embed + pos (float4); 2 tasks/thread
        {
            const float4* e4 = (const float4*)embed;
            const float4* p4 = (const float4*)pos;
            float4* es4 = (float4*)es;
            float4* qs4 = (float4*)qs;
#pragma unroll
            for (int s = 0; s < 2; s++) {
                int idx = t + s * THR;                   // < 512
                int tk = idx >> 5, c4 = idx & 31;
                size_t off = ((size_t)tok_b[tk] * NTOK + tok_n[tk]) * (C / 4) + c4;
                float4 e = e4[off], p = p4[off];
                es4[idx] = e;
                float4 q = {e.x + p.x, e.y + p.y, e.z + p.z, e.w + p.w};
                qs4[idx] = q;
            }
        }
        __syncthreads();

        // phase 2: P = q @ [Woff | Ww] + bias (8-token blocking, k x4)
        for (int it = t; it < NCOL * 2; it += THR) {
            int j = it % NCOL, tg = it / NCOL;
            const float* W; int ld; float bias;
            if (j < NOFF) { W = Woff + j; ld = NOFF; bias = boff[j]; }
            else          { W = Ww + (j - NOFF); ld = NW; bias = bw[j - NOFF]; }
            const float* qrow = qs + tg * 8 * C;
            float acc[8];
#pragma unroll
            for (int tt = 0; tt < 8; tt++) acc[tt] = 0.f;
            for (int k4 = 0; k4 < C / 4; k4++) {
                float w0 = W[(k4 * 4 + 0) * ld];
                float w1 = W[(k4 * 4 + 1) * ld];
                float w2 = W[(k4 * 4 + 2) * ld];
                float w3 = W[(k4 * 4 + 3) * ld];
#pragma unroll
                for (int tt = 0; tt < 8; tt++) {
                    float4 qv = *(const float4*)(qrow + tt * C + k4 * 4);
                    acc[tt] += qv.x * w0 + qv.y * w1 + qv.z * w2 + qv.w * w3;
                }
            }
#pragma unroll
            for (int tt = 0; tt < 8; tt++) P[(tg * 8 + tt) * NCOL + j] = acc[tt] + bias;
        }
        __syncthreads();

        // phase 3: softmax over 12 per (token, head)
        if (t < TOK * HEADS) {
            float* wv = P + (t >> 3) * NCOL + NOFF + (t & 7) * 12;
            float m = wv[0];
#pragma unroll
            for (int i = 1; i < 12; i++) m = fmaxf(m, wv[i]);
            float e[12], s = 0.f;
#pragma unroll
            for (int i = 0; i < 12; i++) { e[i] = expf(wv[i] - m); s += e[i]; }
            float r = 1.f / s;
#pragma unroll
            for (int i = 0; i < 12; i++) wv[i] = e[i] * r;
        }
        __syncthreads();

        // phase 4a: sample params; reg-staged then written over dead P
        {
            float rfx[6], rg0[6], rg1[6];
#pragma unroll
            for (int s = 0; s < 6; s++) {
                int it = t + s * THR;                    // < 1536
                int tk = it / NW, rem = it % NW;
                int h = rem / 12, lp = rem % 12, l = lp >> 2;
                float wl = (l == 0) ? (float)W0 : (l == 1) ? (float)W1 : (float)W2;
                float hl = (l == 0) ? (float)H0 : (l == 1) ? (float)H1 : (float)H2;
                int jo = ((h * 3 + l) * 4 + (lp & 3)) * 2;
                float offx = P[tk * NCOL + jo];
                float offy = P[tk * NCOL + jo + 1];
                float a = P[tk * NCOL + NOFF + rem];
                float x = rpx[tk] * wl + offx - 0.5f;
                float y = rpy[tk] * hl + offy - 0.5f;
                float x0 = floorf(x), y0 = floorf(y);
                sp_xy[it] = (((int)y0 & 0xffff) << 16) | ((int)x0 & 0xffff);
                rfx[s] = x - x0;
                float fy = y - y0;
                rg0[s] = (1.f - fy) * a;
                rg1[s] = fy * a;
            }
            __syncthreads();
#pragma unroll
            for (int s = 0; s < 6; s++) {
                int it = t + s * THR;
                spF[it] = rfx[s];
                spG0[it] = rg0[s];
                spG1[it] = rg1[s];
            }
        }
        __syncthreads();

        // phase 4: bilinear gather + accumulate (thread owns channel c for 8 tokens)
        {
            const int c = t & 127, tg = t >> 7, h = c >> 4;
            for (int tt = 0; tt < 8; tt++) {
                int tk = tg * 8 + tt;
                const float* vb = g_value + (size_t)tok_b[tk] * NPIX * C + c;
                int sbase = tk * NW + h * 12;
                float acc = 0.f;
#pragma unroll
                for (int lp = 0; lp < 12; lp++) {
                    const int l = lp >> 2;
                    const int wl = (l == 0) ? W0 : (l == 1) ? W1 : W2;
                    const int hh = (l == 0) ? H0 : (l == 1) ? H1 : H2;
                    const int st = (l == 0) ? 0 : (l == 1) ? S1 : S2;
                    int pxy = sp_xy[sbase + lp];
                    int xi = (int)(short)(pxy & 0xffff);
                    int yi = pxy >> 16;
                    float fx = spF[sbase + lp];
                    float g0 = spG0[sbase + lp];
                    float g1 = spG1[sbase + lp];
                    int vx0 = (xi >= 0) & (xi < wl);
                    int vx1 = (xi >= -1) & (xi < wl - 1);
                    int vy0 = (yi >= 0) & (yi < hh);
                    int vy1 = (yi >= -1) & (yi < hh - 1);
                    int xc0 = min(max(xi, 0), wl - 1);
                    int xc1 = min(max(xi + 1, 0), wl - 1);
                    int yc0 = min(max(yi, 0), hh - 1);
                    int yc1 = min(max(yi + 1, 0), hh - 1);
                    const float* r0p = vb + (size_t)(st + yc0 * wl) * C;
                    const float* r1p = vb + (size_t)(st + yc1 * wl) * C;
                    float v00 = r0p[(size_t)xc0 * C];
                    float v10 = r0p[(size_t)xc1 * C];
                    float v01 = r1p[(size_t)xc0 * C];
                    float v11 = r1p[(size_t)xc1 * C];
                    float wx0 = 1.f - fx;
                    float w00 = (vx0 & vy0) ? wx0 * g0 : 0.f;
                    float w10 = (vx1 & vy0) ? fx * g0 : 0.f;
                    float w01 = (vx0 & vy1) ? wx0 * g1 : 0.f;
                    float w11 = (vx1 & vy1) ? fx * g1 : 0.f;
                    acc += v00 * w00 + v10 * w10 + v01 * w01 + v11 * w11;
                }
                accs[tk * C + c] = acc;
            }
        }
        __syncthreads();

        // phase 5: out = accs @ Wo + bo + identity (8-token blocking, k x4)
        {
            const int c = t & 127, tg = t >> 7;
            const float* arow = accs + tg * 8 * C;
            float o[8];
#pragma unroll
            for (int tt = 0; tt < 8; tt++) o[tt] = 0.f;
            for (int k4 = 0; k4 < C / 4; k4++) {
                float w0 = Wo[(k4 * 4 + 0) * C + c];
                float w1 = Wo[(k4 * 4 + 1) * C + c];
                float w2 = Wo[(k4 * 4 + 2) * C + c];
                float w3 = Wo[(k4 * 4 + 3) * C + c];
#pragma unroll
                for (int tt = 0; tt < 8; tt++) {
                    float4 av = *(const float4*)(arow + tt * C + k4 * 4);
                    o[tt] += av.x * w0 + av.y * w1 + av.z * w2 + av.w * w3;
                }
            }
            float bias = bo[c];
#pragma unroll
            for (int tt = 0; tt < 8; tt++) {
                int tk = tg * 8 + tt;
                outs[tk * C + c] = o[tt] + bias + es[tk * C + c];
            }
        }
        __syncthreads();

        // LayerNorm stats: warp per token, shuffle reduce (8 warps x 2 tokens)
        {
            int w0id = t >> 5, lane = t & 31;
            for (int w = w0id; w < TOK; w += 8) {
                float v0 = outs[w * C + lane];
                float v1 = outs[w * C + lane + 32];
                float v2 = outs[w * C + lane + 64];
                float v3 = outs[w * C + lane + 96];
                float s = v0 + v1 + v2 + v3;
                float s2 = v0 * v0 + v1 * v1 + v2 * v2 + v3 * v3;
#pragma unroll
                for (int d = 16; d > 0; d >>= 1) {
                    s  += __shfl_xor_sync(0xffffffff, s, d);
                    s2 += __shfl_xor_sync(0xffffffff, s2, d);
                }
                if (lane == 0) {
                    float mu = s * (1.f / C);
                    float var = s2 * (1.f / C) - mu * mu;
                    s_mu[w] = mu;
                    s_inv[w] = rsqrtf(var + 1e-5f);
                }
            }
        }
        __syncthreads();

        // normalized scatter-write into transposed output
        int nt = min(TOK, cnt - base);
        for (int idx = t; idx < nt * C; idx += THR) {
            int tk = idx >> 7, cc = idx & 127;
            float v = (outs[tk * C + cc] - s_mu[tk]) * s_inv[tk] * ln_g[cc] + ln_b[cc];
            out[((size_t)tok_b[tk] * C + cc) * NTOK + tok_n[tk]] = v;
        }
        __syncthreads();   // protect smem reuse for next tile
    }
}

// ---------------- launcher ----------------
extern "C" void kernel_launch(void* const* d_in, const int* in_sizes, int n_in,
                              void* d_out, int out_size)
{
    // bind inputs by element count (robust to metadata ordering)
    const float *embed = 0, *pos = 0, *refpix = 0;
    const float *f0 = 0, *f1 = 0, *f2 = 0;
    const float *Wv = 0, *bv = 0, *Woff = 0, *boff = 0, *Ww = 0, *bw = 0;
    const float *Wo = 0, *bo = 0, *lng = 0, *lnb = 0;
    const int* vol = 0;
    int seen_big = 0, seen_16384 = 0, seen_128 = 0;
    for (int i = 0; i < n_in; i++) {
        int s = in_sizes[i];
        const float* p = (const float*)d_in[i];
        switch (s) {
            case 33554432: if (seen_big++ == 0) embed = p; else pos = p; break;
            case 786432:   vol = (const int*)d_in[i]; break;
            case 524288:   refpix = p; break;
            case 1840896:  f0 = p; break;
            case 473088:   f1 = p; break;
            case 119808:   f2 = p; break;
            case 16384:    if (seen_16384++ == 0) Wv = p; else Wo = p; break;
            case 24576:    Woff = p; break;
            case 192:      boff = p; break;
            case 12288:    Ww = p; break;
            case 96:       bw = p; break;
            case 128: {
                int k = seen_128++;
                if (k == 0) bv = p; else if (k == 1) bo = p;
                else if (k == 2) lng = p; else lnb = p;
                break;
            }
            default: break;
        }
    }
    float* out = (float*)d_out;

    const int PREP_SMEM = 49152;                                // value blocks: 48KB
    const int MAIN_SMEM = (TOK * C * 2 + TOK * NCOL) * 4;       // 34816 B
    cudaFuncSetAttribute(k_prep, cudaFuncAttributeMaxDynamicSharedMemorySize, PREP_SMEM);
    cudaFuncSetAttribute(k_main, cudaFuncAttributeMaxDynamicSharedMemorySize, MAIN_SMEM);

    k_zero<<<BB * NTOK / (4 * 256), 256>>>();
    k_prep<<<NV + NSCAT, THR, PREP_SMEM>>>(f0, f1, f2, Wv, bv, vol);
    k_main<<<NATTN + NFILL, THR, MAIN_SMEM>>>(embed, pos, refpix, Woff, boff, Ww, bw,
                                              Wo, bo, lng, lnb, out);
}

// round 15
// speedup vs baseline: 1.4293x; 1.2586x over previous
#include <cuda_runtime.h>
#include <cuda_fp16.h>
#include <stdint.h>

#define XD 128
#define YD 128
#define ZD 8
#define NTOK 131072          // XD*YD*ZD
#define BB 2
#define C 128
#define HEADS 8
#define LEVELS 3
#define POINTS 4
#define NOFF 192             // HEADS*LEVELS*POINTS*2
#define NW 96                // HEADS*LEVELS*POINTS
#define NCOL 288             // NOFF+NW
#define NPIX 9507
#define H0 47
#define W0 153
#define H1 24
#define W1 77
#define H2 12
#define W2 39
#define S1 7191              // H0*W0
#define S2 9039              // S1 + H1*W1

#define TOK 16
#define THR 256
#define NV 298               // ceil(BB*NPIX / 64) value blocks in fused kernel
#define NFILL 8192           // (NTOK/32)*BB fill blocks

// ---------------- scratch (static device globals; no allocation) ----------------
__device__ float g_value[(size_t)BB * NPIX * C];       // ~9.3 MB, mostly L2-resident
__device__ int g_mask[BB * NTOK];
__device__ int g_list[BB * NTOK];
__device__ int g_cnt;

// ---------------- K1: zero mask + counter ----------------
__global__ void k_zero() {
    int i = blockIdx.x * blockDim.x + threadIdx.x;   // 65536 threads x int4
    ((int4*)g_mask)[i] = make_int4(0, 0, 0, 0);
    if (i == 0) g_cnt = 0;
}

// ---------------- K2: fused scatter + compact (atomicExch dedupe) ----------------
__global__ void k_scatcomp(const int* __restrict__ vol) {
    int i = blockIdx.x * blockDim.x + threadIdx.x;
    if (i >= BB * NTOK) return;
    int x = vol[3 * i], y = vol[3 * i + 1], z = vol[3 * i + 2];
    if ((unsigned)x < XD && (unsigned)y < YD && (unsigned)z < ZD) {
        int b = i >> 17;
        int v = b * NTOK + x * (YD * ZD) + y * ZD + z;
        if (atomicExch(&g_mask[v], 1) == 0) {
            int p = atomicAdd(&g_cnt, 1);
            g_list[p] = v;
        }
    }
}

// ---------------- K3 (fused): value projection blocks + fill/transpose blocks ----------------
// blocks [0, NV): value projection, 64 px/block, Wv cached in smem in 32-k chunks
// blocks [NV, NV+NFILL): transpose scene_embed into out (swizzled, float4 both sides)
__global__ void __launch_bounds__(THR) k_fillvalue(
    const float4* __restrict__ embed4, float4* __restrict__ out4,
    const float* __restrict__ f0, const float* __restrict__ f1, const float* __restrict__ f2,
    const float* __restrict__ Wv, const float* __restrict__ bv)
{
    extern __shared__ __align__(16) char smbuf[];
    const int t = threadIdx.x;

    if (blockIdx.x < NV) {
        // ================= value projection =================
        float (*fs)[64] = (float(*)[64])smbuf;            // 32 KB
        float* Wvs = (float*)(smbuf + 32768);             // 16 KB: [32][128]
        __shared__ const float* ptrs[64];
        __shared__ int strd[64];
        const int r0 = blockIdx.x * 64;
        const int total = BB * NPIX;

        if (t < 64) {
            int row = r0 + t;
            if (row < total) {
                int b = row / NPIX, pix = row % NPIX;
                const float* f; int HW, hw;
                if (pix < S1)      { f = f0; HW = H0 * W0; hw = pix; }
                else if (pix < S2) { f = f1; HW = H1 * W1; hw = pix - S1; }
                else               { f = f2; HW = H2 * W2; hw = pix - S2; }
                ptrs[t] = f + (size_t)b * C * HW + hw;
                strd[t] = HW;
            } else { ptrs[t] = f0; strd[t] = 0; }
        }
        __syncthreads();

#pragma unroll
        for (int i = 0; i < 32; i++) {                    // C*64/THR = 32 loads/thread
            int idx = t + i * THR;
            int k = idx >> 6, j = idx & 63;
            fs[k][j] = ptrs[j][(size_t)k * strd[j]];
        }
        __syncthreads();

        const int cg = t & 31;                            // float4 channel group
        const int p0 = (t >> 5) * 8;                      // 8 pixels
        float acc[4][8];
#pragma unroll
        for (int ci = 0; ci < 4; ci++)
#pragma unroll
            for (int p = 0; p < 8; p++) acc[ci][p] = 0.f;

        for (int kc = 0; kc < 4; kc++) {
            const float4* Wg = (const float4*)(Wv + kc * 32 * C);
            float4* Ws4 = (float4*)Wvs;
#pragma unroll
            for (int i = 0; i < 4; i++) Ws4[t + i * THR] = Wg[t + i * THR];
            __syncthreads();

#pragma unroll
            for (int kk = 0; kk < 32; kk++) {
                int k = kc * 32 + kk;
                float4 w = ((const float4*)(Wvs + kk * C))[cg];
                float4 fa = *(const float4*)&fs[k][p0];
                float4 fb = *(const float4*)&fs[k][p0 + 4];
                float fv[8] = {fa.x, fa.y, fa.z, fa.w, fb.x, fb.y, fb.z, fb.w};
#pragma unroll
                for (int p = 0; p < 8; p++) {
                    acc[0][p] += fv[p] * w.x;
                    acc[1][p] += fv[p] * w.y;
                    acc[2][p] += fv[p] * w.z;
                    acc[3][p] += fv[p] * w.w;
                }
            }
            __syncthreads();
        }

        float4 bias = ((const float4*)bv)[cg];
        float4* gv4 = (float4*)g_value;
#pragma unroll
        for (int p = 0; p < 8; p++) {
            int row = r0 + p0 + p;
            if (row < total) {
                float4 o;
                o.x = acc[0][p] + bias.x;
                o.y = acc[1][p] + bias.y;
                o.z = acc[2][p] + bias.z;
                o.w = acc[3][p] + bias.w;
                gv4[(size_t)row * (C / 4) + cg] = o;
            }
        }
    } else {
        // ================= fill / transpose =================
        float (*tile)[33] = (float(*)[33])smbuf;          // 16.9 KB
        const int vb = blockIdx.x - NV;
        const int n0 = (vb & 4095) * 32, b = vb >> 12;

        {
            const int nl = t >> 5;
            const int c4 = t & 31;
#pragma unroll
            for (int r = 0; r < 4; r++) {
                int n = nl + r * 8;
                float4 v = embed4[((size_t)b * NTOK + n0 + n) * (C / 4) + c4];
                int col = (n + c4) & 31;
                tile[c4 * 4 + 0][col] = v.x;
                tile[c4 * 4 + 1][col] = v.y;
                tile[c4 * 4 + 2][col] = v.z;
                tile[c4 * 4 + 3][col] = v.w;
            }
        }
        __syncthreads();

#pragma unroll
        for (int r = 0; r < 4; r++) {
            int idx = t + r * THR;
            int c = idx >> 3, n4 = idx & 7;
            int rot = c >> 2;
            float4 w;
            w.x = tile[c][(n4 * 4 + 0 + rot) & 31];
            w.y = tile[c][(n4 * 4 + 1 + rot) & 31];
            w.z = tile[c][(n4 * 4 + 2 + rot) & 31];
            w.w = tile[c][(n4 * 4 + 3 + rot) & 31];
            out4[(((size_t)b * C + c) * NTOK + n0) / 4 + n4] = w;
        }
    }
}

// ---------------- K4: deformable attention on compacted tokens ----------------
// R8 layout (34816 B dynamic + ~6.7 KB static -> 5 blocks/SM); ONLY 4a/gather changed:
// per-sample precompute packs (row0*C | deltaFlag<<31) into static sp_xy, and
// (xc0*C | xc1*C<<16) + 2x half2 validity-folded corner weights into the P overlay.
__global__ void __launch_bounds__(THR, 5) k_attn(
    const float* __restrict__ embed, const float* __restrict__ pos,
    const float* __restrict__ refpix,
    const float* __restrict__ Woff, const float* __restrict__ boff,
    const float* __restrict__ Ww, const float* __restrict__ bw,
    const float* __restrict__ Wo, const float* __restrict__ bo,
    const float* __restrict__ ln_g, const float* __restrict__ ln_b,
    float* __restrict__ out)
{
    extern __shared__ float sm[];
    float* qs    = sm;                        // TOK*C      (reused as accs)
    float* es    = qs + TOK * C;              // TOK*C
    float* P     = es + TOK * C;              // TOK*NCOL   (reused below after 4a)
    int*   spIB  = (int*)P;                   // [0,1536): xc0*C | xc1*C<<16
    __half2* spW0 = (__half2*)(P + 1536);     // (w00, w10)
    __half2* spW1 = (__half2*)(P + 3072);     // (w01, w11)
    float* accs  = qs;
    float* outs  = P;

    __shared__ int sp_xy[TOK * NW];           // 6144 B static: row0*C | dflag<<31
    __shared__ float rpx[TOK], rpy[TOK], s_mu[TOK], s_inv[TOK];
    __shared__ int tok_b[TOK], tok_n[TOK];
    __shared__ int s_cnt;

    const int t = threadIdx.x;
    if (t == 0) s_cnt = g_cnt;
    __syncthreads();
    const int cnt = s_cnt;

    for (int tile = blockIdx.x; tile * TOK < cnt; tile += gridDim.x) {
        const int base = tile * TOK;

        if (t < TOK) {
            int id = g_list[min(base + t, cnt - 1)];
            tok_b[t] = id >> 17;
            tok_n[t] = id & (NTOK - 1);
            rpx[t] = refpix[(size_t)id * 2];
            rpy[t] = refpix[(size_t)id * 2 + 1];
        }
        __syncthreads();

        // phase 1: q = embed + pos (float4); keep identity
        {
            const float4* e4 = (const float4*)embed;
            const float4* p4 = (const float4*)pos;
            float4* es4 = (float4*)es;
            float4* qs4 = (float4*)qs;
#pragma unroll
            for (int s = 0; s < 2; s++) {
                int idx = t + s * THR;                   // < 512
                int tk = idx >> 5, c4 = idx & 31;
                size_t off = ((size_t)tok_b[tk] * NTOK + tok_n[tk]) * (C / 4) + c4;
                float4 e = e4[off], p = p4[off];
                es4[idx] = e;
                float4 q = {e.x + p.x, e.y + p.y, e.z + p.z, e.w + p.w};
                qs4[idx] = q;
            }
        }
        __syncthreads();

        // phase 2: P = q @ [Woff | Ww] + bias (8-token blocking, k x4)
        for (int it = t; it < NCOL * 2; it += THR) {
            int j = it % NCOL, tg = it / NCOL;
            const float* W; int ld; float bias;
            if (j < NOFF) { W = Woff + j; ld = NOFF; bias = boff[j]; }
            else          { W = Ww + (j - NOFF); ld = NW; bias = bw[j - NOFF]; }
            const float* qrow = qs + tg * 8 * C;
            float acc[8];
#pragma unroll
            for (int tt = 0; tt < 8; tt++) acc[tt] = 0.f;
            for (int k4 = 0; k4 < C / 4; k4++) {
                float w0 = W[(k4 * 4 + 0) * ld];
                float w1 = W[(k4 * 4 + 1) * ld];
                float w2 = W[(k4 * 4 + 2) * ld];
                float w3 = W[(k4 * 4 + 3) * ld];
#pragma unroll
                for (int tt = 0; tt < 8; tt++) {
                    float4 qv = *(const float4*)(qrow + tt * C + k4 * 4);
                    acc[tt] += qv.x * w0 + qv.y * w1 + qv.z * w2 + qv.w * w3;
                }
            }
#pragma unroll
            for (int tt = 0; tt < 8; tt++) P[(tg * 8 + tt) * NCOL + j] = acc[tt] + bias;
        }
        __syncthreads();

        // phase 3: softmax over 12 per (token, head)
        if (t < TOK * HEADS) {
            float* wv = P + (t >> 3) * NCOL + NOFF + (t & 7) * 12;
            float m = wv[0];
#pragma unroll
            for (int i = 1; i < 12; i++) m = fmaxf(m, wv[i]);
            float e[12], s = 0.f;
#pragma unroll
            for (int i = 0; i < 12; i++) { e[i] = expf(wv[i] - m); s += e[i]; }
            float r = 1.f / s;
#pragma unroll
            for (int i = 0; i < 12; i++) wv[i] = e[i] * r;
        }
        __syncthreads();

        // phase 4a: per-sample hoisted bilinear params.
        // sp_xy (static) written directly; intB + 2 half2 weights reg-staged (18 regs, as R8).
        {
            int rib[6];
            __half2 rw0[6], rw1[6];
#pragma unroll
            for (int s = 0; s < 6; s++) {
                int it = t + s * THR;                    // < 1536
                int tk = it / NW, rem = it % NW;
                int h = rem / 12, lp = rem % 12, l = lp >> 2;
                float wlf = (l == 0) ? (float)W0 : (l == 1) ? (float)W1 : (float)W2;
                float hlf = (l == 0) ? (float)H0 : (l == 1) ? (float)H1 : (float)H2;
                int wl = (l == 0) ? W0 : (l == 1) ? W1 : W2;
                int hh = (l == 0) ? H0 : (l == 1) ? H1 : H2;
                int st = (l == 0) ? 0 : (l == 1) ? S1 : S2;
                int jo = ((h * 3 + l) * 4 + (lp & 3)) * 2;
                float offx = P[tk * NCOL + jo];
                float offy = P[tk * NCOL + jo + 1];
                float a = P[tk * NCOL + NOFF + rem];
                float x = rpx[tk] * wlf + offx - 0.5f;
                float y = rpy[tk] * hlf + offy - 0.5f;
                float x0 = floorf(x), y0 = floorf(y);
                int xi = (int)x0, yi = (int)y0;
                float fx = x - x0, fy = y - y0;
                float g0 = (1.f - fy) * a, g1 = fy * a;

                int vx0 = (xi >= 0) & (xi < wl);
                int vx1 = (xi >= -1) & (xi < wl - 1);
                int vy0 = (yi >= 0) & (yi < hh);
                int vy1 = (yi >= -1) & (yi < hh - 1);
                int xc0 = min(max(xi, 0), wl - 1);
                int xc1 = min(max(xi + 1, 0), wl - 1);
                int yc0 = min(max(yi, 0), hh - 1);
                int yc1 = min(max(yi + 1, 0), hh - 1);
                int row0 = tok_b[tk] * NPIX + st + yc0 * wl;
                unsigned dflag = (unsigned)(yc1 - yc0);          // 0 or 1
                sp_xy[it] = (int)((unsigned)(row0 * C) | (dflag << 31));
                rib[s] = (xc0 * C) | ((xc1 * C) << 16);
                float wx0 = 1.f - fx;
                float w00 = (vx0 & vy0) ? wx0 * g0 : 0.f;
                float w10 = (vx1 & vy0) ? fx * g0 : 0.f;
                float w01 = (vx0 & vy1) ? wx0 * g1 : 0.f;
                float w11 = (vx1 & vy1) ? fx * g1 : 0.f;
                rw0[s] = __floats2half2_rn(w00, w10);
                rw1[s] = __floats2half2_rn(w01, w11);
            }
            __syncthreads();     // all P reads done; safe to overwrite P overlay
#pragma unroll
            for (int s = 0; s < 6; s++) {
                int it = t + s * THR;
                spIB[it] = rib[s];
                spW0[it] = rw0[s];
                spW1[it] = rw1[s];
            }
        }
        __syncthreads();

        // phase 4: bilinear gather + accumulate (thread owns channel c for 8 tokens)
        {
            const int c = t & 127, tg = t >> 7, h12 = ((t & 127) >> 4) * 12;
            const float* vb = g_value + c;
            for (int tt = 0; tt < 8; tt++) {
                int tk = tg * 8 + tt;
                int sbase = tk * NW + h12;
                float acc = 0.f;
#pragma unroll
                for (int lp = 0; lp < 12; lp++) {
                    const int l = lp >> 2;
                    const int wlC = ((l == 0) ? W0 : (l == 1) ? W1 : W2) * C;
                    int ia = sp_xy[sbase + lp];
                    int ib = spIB[sbase + lp];
                    float2 wa = __half22float2(spW0[sbase + lp]);
                    float2 wb = __half22float2(spW1[sbase + lp]);
                    const float* p0 = vb + (ia & 0x7fffffff);
                    const float* p1 = p0 + ((ia < 0) ? wlC : 0);
                    int x0c = ib & 0xffff, x1c = ib >> 16;
                    float v00 = p0[x0c], v10 = p0[x1c];
                    float v01 = p1[x0c], v11 = p1[x1c];
                    acc += v00 * wa.x + v10 * wa.y + v01 * wb.x + v11 * wb.y;
                }
                accs[tk * C + c] = acc;
            }
        }
        __syncthreads();

        // phase 5: out = accs @ Wo + bo + identity (8-token blocking, k x4)
        {
            const int c = t & 127, tg = t >> 7;
            const float* arow = accs + tg * 8 * C;
            float o[8];
#pragma unroll
            for (int tt = 0; tt < 8; tt++) o[tt] = 0.f;
            for (int k4 = 0; k4 < C / 4; k4++) {
                float w0 = Wo[(k4 * 4 + 0) * C + c];
                float w1 = Wo[(k4 * 4 + 1) * C + c];
                float w2 = Wo[(k4 * 4 + 2) * C + c];
                float w3 = Wo[(k4 * 4 + 3) * C + c];
#pragma unroll
                for (int tt = 0; tt < 8; tt++) {
                    float4 av = *(const float4*)(arow + tt * C + k4 * 4);
                    o[tt] += av.x * w0 + av.y * w1 + av.z * w2 + av.w * w3;
                }
            }
            float bias = bo[c];
#pragma unroll
            for (int tt = 0; tt < 8; tt++) {
                int tk = tg * 8 + tt;
                outs[tk * C + c] = o[tt] + bias + es[tk * C + c];
            }
        }
        __syncthreads();

        // LayerNorm stats: warp per token, shuffle reduce (8 warps x 2 tokens)
        {
            int w0id = t >> 5, lane = t & 31;
            for (int w = w0id; w < TOK; w += 8) {
                float v0 = outs[w * C + lane];
                float v1 = outs[w * C + lane + 32];
                float v2 = outs[w * C + lane + 64];
                float v3 = outs[w * C + lane + 96];
                float s = v0 + v1 + v2 + v3;
                float s2 = v0 * v0 + v1 * v1 + v2 * v2 + v3 * v3;
#pragma unroll
                for (int d = 16; d > 0; d >>= 1) {
                    s  += __shfl_xor_sync(0xffffffff, s, d);
                    s2 += __shfl_xor_sync(0xffffffff, s2, d);
                }
                if (lane == 0) {
                    float mu = s * (1.f / C);
                    float var = s2 * (1.f / C) - mu * mu;
                    s_mu[w] = mu;
                    s_inv[w] = rsqrtf(var + 1e-5f);
                }
            }
        }
        __syncthreads();

        // normalized scatter-write into transposed output
        int nt = min(TOK, cnt - base);
        for (int idx = t; idx < nt * C; idx += THR) {
            int tk = idx >> 7, cc = idx & 127;
            float v = (outs[tk * C + cc] - s_mu[tk]) * s_inv[tk] * ln_g[cc] + ln_b[cc];
            out[((size_t)tok_b[tk] * C + cc) * NTOK + tok_n[tk]] = v;
        }
        __syncthreads();   // protect smem reuse for next tile
    }
}

// ---------------- launcher ----------------
extern "C" void kernel_launch(void* const* d_in, const int* in_sizes, int n_in,
                              void* d_out, int out_size)
{
    // bind inputs by element count (robust to metadata ordering)
    const float *embed = 0, *pos = 0, *refpix = 0;
    const float *f0 = 0, *f1 = 0, *f2 = 0;
    const float *Wv = 0, *bv = 0, *Woff = 0, *boff = 0, *Ww = 0, *bw = 0;
    const float *Wo = 0, *bo = 0, *lng = 0, *lnb = 0;
    const int* vol = 0;
    int seen_big = 0, seen_16384 = 0, seen_128 = 0;
    for (int i = 0; i < n_in; i++) {
        int s = in_sizes[i];
        const float* p = (const float*)d_in[i];
        switch (s) {
            case 33554432: if (seen_big++ == 0) embed = p; else pos = p; break;
            case 786432:   vol = (const int*)d_in[i]; break;
            case 524288:   refpix = p; break;
            case 1840896:  f0 = p; break;
            case 473088:   f1 = p; break;
            case 119808:   f2 = p; break;
            case 16384:    if (seen_16384++ == 0) Wv = p; else Wo = p; break;
            case 24576:    Woff = p; break;
            case 192:      boff = p; break;
            case 12288:    Ww = p; break;
            case 96:       bw = p; break;
            case 128: {
                int k = seen_128++;
                if (k == 0) bv = p; else if (k == 1) bo = p;
                else if (k == 2) lng = p; else lnb = p;
                break;
            }
            default: break;
        }
    }
    float* out = (float*)d_out;

    const int FV_SMEM = 49152;                                  // value: 48KB; fill uses subset
    const int AT_SMEM = (TOK * C * 2 + TOK * NCOL) * 4;         // 34816 B
    cudaFuncSetAttribute(k_fillvalue, cudaFuncAttributeMaxDynamicSharedMemorySize, FV_SMEM);
    cudaFuncSetAttribute(k_attn, cudaFuncAttributeMaxDynamicSharedMemorySize, AT_SMEM);

    k_zero<<<BB * NTOK / (4 * 256), 256>>>();
    k_scatcomp<<<(BB * NTOK + 255) / 256, 256>>>(vol);
    k_fillvalue<<<NV + NFILL, THR, FV_SMEM>>>(
        (const float4*)embed, (float4*)out, f0, f1, f2, Wv, bv);
    k_attn<<<1024, THR, AT_SMEM>>>(embed, pos, refpix, Woff, boff, Ww, bw,
                                   Wo, bo, lng, lnb, out);
}